// round 8
// baseline (speedup 1.0000x reference)
#include <cuda_runtime.h>
#include <cstdint>

#define NC     4                 // cluster size (CTAs)
#define T      512               // threads per CTA
#define NWARP  (T / 32)          // 16 warps
#define VPT    8                 // elements per thread: NC*T*VPT = 16384

__device__ __forceinline__ uint32_t ctarank() {
    uint32_t r; asm("mov.u32 %0, %%cluster_ctarank;" : "=r"(r)); return r;
}
__device__ __forceinline__ uint32_t smem_u32(const void* p) {
    return (uint32_t)__cvta_generic_to_shared(p);
}
__device__ __forceinline__ void st_cluster_v2(void* local_slot, uint32_t rank,
                                              float x, float y) {
    uint32_t rslot;
    asm("mapa.shared::cluster.u32 %0, %1, %2;"
        : "=r"(rslot) : "r"(smem_u32(local_slot)), "r"(rank));
    asm volatile("st.shared::cluster.v2.f32 [%0], {%1, %2};"
                 :: "r"(rslot), "f"(x), "f"(y) : "memory");
}
__device__ __forceinline__ void st_cluster_f32(void* local_slot, uint32_t rank, float x) {
    uint32_t rslot;
    asm("mapa.shared::cluster.u32 %0, %1, %2;"
        : "=r"(rslot) : "r"(smem_u32(local_slot)), "r"(rank));
    asm volatile("st.shared::cluster.f32 [%0], %1;" :: "r"(rslot), "f"(x) : "memory");
}
__device__ __forceinline__ void cluster_sync_() {
    asm volatile("barrier.cluster.arrive.aligned;" ::: "memory");
    asm volatile("barrier.cluster.wait.aligned;"   ::: "memory");
}

__global__ __launch_bounds__(T, 1) __cluster_dims__(NC, 1, 1)
void nll_cluster(const float4* __restrict__ pred4,
                 const float4* __restrict__ label4,
                 float* __restrict__ out, int out_size) {
    const int t = threadIdx.x;
    const unsigned lane = t & 31u;
    const unsigned wid  = t >> 5;
    const uint32_t rank = ctarank();

    __shared__ float2 s_tot[NC];        // (ctaTotal, ctaCnt) from each CTA
    __shared__ float  s_red[NC];        // partial c, gathered at CTA0
    __shared__ float  s_warp[NWARP];    // warp scan totals
    __shared__ float  s_rc[NWARP];      // warp cnt / c partials

    // ---------------- all loads issued up front (MLP = 6) -------------------
    const int g = (int)rank * T + t;
    float4 pa = pred4[g * 2 + 0];
    float4 pb = pred4[g * 2 + 1];
    float4 l0 = label4[g * 4 + 0];
    float4 l1 = label4[g * 4 + 1];
    float4 l2 = label4[g * 4 + 2];
    float4 l3 = label4[g * 4 + 3];

    float p[VPT]  = {pa.x, pa.y, pa.z, pa.w, pb.x, pb.y, pb.z, pb.w};
    float ev[VPT] = {l0.y, l0.w, l1.y, l1.w, l2.y, l2.w, l3.y, l3.w};

    // ---------------- exp + local inclusive scan + local cnt ----------------
    float r[VPT];
    float cnt = 0.f;
    {
        float run = 0.f;
        #pragma unroll
        for (int k = 0; k < VPT; k++) {
            run += __expf(p[k]);
            r[k] = run;
            cnt += ev[k];
        }
    }
    const float tot = r[VPT - 1];

    // ---------------- warp scan of totals + warp reduce of cnt --------------
    float ws = tot;
    #pragma unroll
    for (int o = 1; o < 32; o <<= 1) {
        float n = __shfl_up_sync(0xffffffffu, ws, o);
        if (lane >= (unsigned)o) ws += n;
    }
    float wc = cnt;
    #pragma unroll
    for (int o = 16; o > 0; o >>= 1) wc += __shfl_down_sync(0xffffffffu, wc, o);
    if (lane == 31) s_warp[wid] = ws;
    if (lane == 0)  s_rc[wid]   = wc;
    __syncthreads();

    // ---------------- cross-warp scan + round-1 send (warp 0) ---------------
    if (wid == 0) {
        float w = (lane < NWARP) ? s_warp[lane] : 0.f;
        #pragma unroll
        for (int o = 1; o < NWARP; o <<= 1) {
            float n = __shfl_up_sync(0xffffffffu, w, o);
            if (lane >= (unsigned)o) w += n;
        }
        if (lane < NWARP) s_warp[lane] = w;

        float cc = (lane < NWARP) ? s_rc[lane] : 0.f;
        #pragma unroll
        for (int o = 8; o > 0; o >>= 1) cc += __shfl_down_sync(0xffffffffu, cc, o);

        const float ctaTotal = __shfl_sync(0xffffffffu, w,  NWARP - 1);
        const float ctaCnt   = __shfl_sync(0xffffffffu, cc, 0);
        if (lane < NC)
            st_cluster_v2(&s_tot[rank], lane, ctaTotal, ctaCnt);
    }
    __syncthreads();
    const float P = (wid ? s_warp[wid - 1] : 0.f) + (ws - tot);

    // ---------------- cluster barrier #1: all-to-all totals ready -----------
    cluster_sync_();

    float ctaExcl = 0.f;
    #pragma unroll
    for (int j = 0; j < NC; j++)
        if ((unsigned)j < rank) ctaExcl += s_tot[j].x;

    // ---------------- contributions, branchless (log is MUFU, cheap) --------
    const float base = ctaExcl + P;
    float c = 0.f;
    #pragma unroll
    for (int k = 0; k < VPT; k++) {
        c += ev[k] * (p[k] - __logf(base + r[k]));
    }

    // ---------------- CTA reduce of c + round-2 send ------------------------
    #pragma unroll
    for (int o = 16; o > 0; o >>= 1) c += __shfl_down_sync(0xffffffffu, c, o);
    if (lane == 0) s_rc[wid] = c;
    __syncthreads();
    if (t == 0) {
        float bc = 0.f;
        #pragma unroll
        for (int w = 0; w < NWARP; w++) bc += s_rc[w];
        st_cluster_f32(&s_red[rank], 0u, bc);
    }

    // ---------------- cluster barrier #2: partials delivered ----------------
    cluster_sync_();

    if (rank == 0 && t == 0) {
        float cs = 0.f, ys = 0.f;
        #pragma unroll
        for (int j = 0; j < NC; j++) { cs += s_red[j]; ys += s_tot[j].y; }
        float cost = (ys == 0.f) ? 0.f : -(cs / fmaxf(ys, 1.f));
        out[0] = cost;
        if (out_size > 1) out[1] = ys;
    }
}

extern "C" void kernel_launch(void* const* d_in, const int* in_sizes, int n_in,
                              void* d_out, int out_size) {
    const float4* pred4  = (const float4*)d_in[0];
    const float4* label4 = (const float4*)d_in[1];
    float* out = (float*)d_out;

    nll_cluster<<<NC, T>>>(pred4, label4, out, out_size);
}

// round 9
// speedup vs baseline: 1.2963x; 1.2963x over previous
#include <cuda_runtime.h>
#include <cstdint>

#define NC     8                 // cluster size (CTAs)
#define T      256               // threads per CTA
#define NWARP  (T / 32)          // 8 warps
#define VPT    8                 // elements per thread: NC*T*VPT = 16384

__device__ __forceinline__ uint32_t ctarank() {
    uint32_t r; asm("mov.u32 %0, %%cluster_ctarank;" : "=r"(r)); return r;
}
__device__ __forceinline__ uint32_t smem_u32(const void* p) {
    return (uint32_t)__cvta_generic_to_shared(p);
}
__device__ __forceinline__ void st_cluster_v2(void* local_slot, uint32_t rank,
                                              float x, float y) {
    uint32_t rslot;
    asm("mapa.shared::cluster.u32 %0, %1, %2;"
        : "=r"(rslot) : "r"(smem_u32(local_slot)), "r"(rank));
    asm volatile("st.shared::cluster.v2.f32 [%0], {%1, %2};"
                 :: "r"(rslot), "f"(x), "f"(y) : "memory");
}
__device__ __forceinline__ void red_add_f32(float* p, float v) {
    asm volatile("red.global.gpu.add.f32 [%0], %1;" :: "l"(p), "f"(v) : "memory");
}

__global__ __launch_bounds__(T, 1) __cluster_dims__(NC, 1, 1)
void nll_cluster(const float4* __restrict__ pred4,
                 const float4* __restrict__ label4,
                 float* __restrict__ out, int out_size) {
    const int t = threadIdx.x;
    const unsigned lane = t & 31u;
    const unsigned wid  = t >> 5;
    const uint32_t rank = ctarank();

    __shared__ float2 s_tot[NC];        // (ctaTotal, ctaCnt) from each CTA
    __shared__ float  s_warp[NWARP];    // warp scan totals
    __shared__ float  s_rc[NWARP];      // warp cnt / c partials

    // ---------------- all loads issued up front (MLP = 6) -------------------
    const int g = (int)rank * T + t;
    float4 pa = pred4[g * 2 + 0];
    float4 pb = pred4[g * 2 + 1];
    float4 l0 = label4[g * 4 + 0];
    float4 l1 = label4[g * 4 + 1];
    float4 l2 = label4[g * 4 + 2];
    float4 l3 = label4[g * 4 + 3];

    // zero the accumulator each launch, strictly before CTA0's barrier arrive
    if (rank == 0 && t == 0) out[0] = 0.f;

    float p[VPT]  = {pa.x, pa.y, pa.z, pa.w, pb.x, pb.y, pb.z, pb.w};
    float ev[VPT] = {l0.y, l0.w, l1.y, l1.w, l2.y, l2.w, l3.y, l3.w};

    // ---------------- exp + local inclusive scan + local cnt ----------------
    float r[VPT];
    float cnt = 0.f;
    {
        float run = 0.f;
        #pragma unroll
        for (int k = 0; k < VPT; k++) {
            run += __expf(p[k]);
            r[k] = run;
            cnt += ev[k];
        }
    }
    const float tot = r[VPT - 1];

    // ---------------- warp scan of totals + warp reduce of cnt --------------
    float ws = tot;
    #pragma unroll
    for (int o = 1; o < 32; o <<= 1) {
        float n = __shfl_up_sync(0xffffffffu, ws, o);
        if (lane >= (unsigned)o) ws += n;
    }
    float wc = cnt;
    #pragma unroll
    for (int o = 16; o > 0; o >>= 1) wc += __shfl_down_sync(0xffffffffu, wc, o);
    if (lane == 31) s_warp[wid] = ws;
    if (lane == 0)  s_rc[wid]   = wc;
    __syncthreads();

    // ---------------- warp 0: cross-warp scan + round-1 DSMEM send ----------
    if (wid == 0) {
        float w = (lane < NWARP) ? s_warp[lane] : 0.f;
        #pragma unroll
        for (int o = 1; o < NWARP; o <<= 1) {
            float n = __shfl_up_sync(0xffffffffu, w, o);
            if (lane >= (unsigned)o) w += n;
        }
        if (lane < NWARP) s_warp[lane] = w;

        float cc = (lane < NWARP) ? s_rc[lane] : 0.f;
        #pragma unroll
        for (int o = 4; o > 0; o >>= 1) cc += __shfl_down_sync(0xffffffffu, cc, o);

        const float ctaTotal = __shfl_sync(0xffffffffu, w,  NWARP - 1);
        const float ctaCnt   = __shfl_sync(0xffffffffu, cc, 0);
        if (lane < NC)
            st_cluster_v2(&s_tot[rank], lane, ctaTotal, ctaCnt);
    }

    // ---------------- single cluster barrier (split arrive/wait) ------------
    // warp0 arrives after its sends (release orders them); other warps arrive
    // immediately. The acquire at wait also publishes warp0's s_warp writes,
    // replacing a second __syncthreads.
    asm volatile("barrier.cluster.arrive.aligned;" ::: "memory");
    asm volatile("barrier.cluster.wait.aligned;"   ::: "memory");

    const float P = (wid ? s_warp[wid - 1] : 0.f) + (ws - tot);

    float ctaExcl = 0.f, nObs = 0.f;
    #pragma unroll
    for (int j = 0; j < NC; j++) {
        if ((unsigned)j < rank) ctaExcl += s_tot[j].x;
        nObs += s_tot[j].y;
    }

    // ---------------- masked contributions (fast log) -----------------------
    const float base = ctaExcl + P;
    float c = 0.f;
    #pragma unroll
    for (int k = 0; k < VPT; k++) {
        if (ev[k] != 0.f) c += ev[k] * (p[k] - __logf(base + r[k]));
    }

    // ---------------- CTA reduce of c, then fire-and-forget REDG ------------
    #pragma unroll
    for (int o = 16; o > 0; o >>= 1) c += __shfl_down_sync(0xffffffffu, c, o);
    if (lane == 0) s_rc[wid] = c;
    __syncthreads();
    if (t == 0) {
        float bc = 0.f;
        #pragma unroll
        for (int w = 0; w < NWARP; w++) bc += s_rc[w];
        const float scale = (nObs == 0.f) ? 0.f : (-1.f / fmaxf(nObs, 1.f));
        red_add_f32(&out[0], bc * scale);     // no-return atomic; no waiting
        if (rank == 0 && out_size > 1) out[1] = nObs;
    }
}

extern "C" void kernel_launch(void* const* d_in, const int* in_sizes, int n_in,
                              void* d_out, int out_size) {
    const float4* pred4  = (const float4*)d_in[0];
    const float4* label4 = (const float4*)d_in[1];
    float* out = (float*)d_out;

    nll_cluster<<<NC, T>>>(pred4, label4, out, out_size);
}

// round 11
// speedup vs baseline: 1.3527x; 1.0435x over previous
#include <cuda_runtime.h>
#include <cstdint>

#define NC     8                 // cluster size (CTAs)
#define T      256               // threads per CTA
#define NWARP  (T / 32)          // 8 warps
#define VPT    8                 // elements per thread: NC*T*VPT = 16384

__device__ __forceinline__ uint32_t ctarank() {
    uint32_t r; asm("mov.u32 %0, %%cluster_ctarank;" : "=r"(r)); return r;
}
__device__ __forceinline__ uint32_t smem_u32(const void* p) {
    return (uint32_t)__cvta_generic_to_shared(p);
}
__device__ __forceinline__ void st_cluster_v2(void* local_slot, uint32_t rank,
                                              float x, float y) {
    uint32_t rslot;
    asm("mapa.shared::cluster.u32 %0, %1, %2;"
        : "=r"(rslot) : "r"(smem_u32(local_slot)), "r"(rank));
    asm volatile("st.shared::cluster.v2.f32 [%0], {%1, %2};"
                 :: "r"(rslot), "f"(x), "f"(y) : "memory");
}
__device__ __forceinline__ void red_add_f32(float* p, float v) {
    asm volatile("red.global.gpu.add.f32 [%0], %1;" :: "l"(p), "f"(v) : "memory");
}
// warp-wide sum via butterfly shuffle; result identical in all lanes
__device__ __forceinline__ float warp_sum(float v) {
    #pragma unroll
    for (int o = 16; o > 0; o >>= 1)
        v += __shfl_xor_sync(0xffffffffu, v, o);
    return v;
}

__global__ __launch_bounds__(T, 1) __cluster_dims__(NC, 1, 1)
void nll_cluster(const float4* __restrict__ pred4,
                 const float4* __restrict__ label4,
                 float* __restrict__ out, int out_size) {
    const int t = threadIdx.x;
    const unsigned lane = t & 31u;
    const unsigned wid  = t >> 5;
    const uint32_t rank = ctarank();

    __shared__ float2 s_tot[NC];       // (ctaTotal, ctaCnt) from each CTA
    __shared__ float  s_warp[NWARP];   // per-warp totals of exp
    __shared__ float  s_rc[NWARP];     // per-warp counts

    // ---------------- all loads issued up front (MLP = 6) -------------------
    const int g = (int)rank * T + t;
    float4 pa = pred4[g * 2 + 0];
    float4 pb = pred4[g * 2 + 1];
    float4 l0 = label4[g * 4 + 0];
    float4 l1 = label4[g * 4 + 1];
    float4 l2 = label4[g * 4 + 2];
    float4 l3 = label4[g * 4 + 3];

    // zero the accumulator each launch, strictly before CTA0's barrier arrive
    if (rank == 0 && t == 0) out[0] = 0.f;

    float p[VPT]  = {pa.x, pa.y, pa.z, pa.w, pb.x, pb.y, pb.z, pb.w};
    float ev[VPT] = {l0.y, l0.w, l1.y, l1.w, l2.y, l2.w, l3.y, l3.w};

    // ---------------- exp + local inclusive scan + local cnt ----------------
    float r[VPT];
    float cnt = 0.f;
    {
        float run = 0.f;
        #pragma unroll
        for (int k = 0; k < VPT; k++) {
            run += __expf(p[k]);
            r[k] = run;
            cnt += ev[k];
        }
    }
    const float tot = r[VPT - 1];

    // ---------------- fast warp totals (butterfly, no scan yet) -------------
    const float wtot = warp_sum(tot);
    const float wcnt = warp_sum(cnt);
    if (lane == 0) { s_warp[wid] = wtot; s_rc[wid] = wcnt; }
    __syncthreads();

    // ---------------- warp 0: CTA totals + round-1 DSMEM send ---------------
    if (wid == 0) {
        float tv = (lane < NWARP) ? s_warp[lane] : 0.f;
        float cv = (lane < NWARP) ? s_rc[lane]   : 0.f;
        const float ctaTotal = warp_sum(tv);
        const float ctaCnt   = warp_sum(cv);
        if (lane < NC)
            st_cluster_v2(&s_tot[rank], lane, ctaTotal, ctaCnt);
    }

    // arrive early; the local scan below overlaps the cluster barrier latency
    asm volatile("barrier.cluster.arrive.aligned;" ::: "memory");

    // ---------------- overlapped: intra-warp scan + warp prefix -------------
    float ws = tot;
    #pragma unroll
    for (int o = 1; o < 32; o <<= 1) {
        float n = __shfl_up_sync(0xffffffffu, ws, o);
        if (lane >= (unsigned)o) ws += n;
    }
    float warpPrefix = 0.f;
    #pragma unroll
    for (int w = 0; w < NWARP; w++)
        if ((unsigned)w < wid) warpPrefix += s_warp[w];
    const float P = warpPrefix + (ws - tot);   // exclusive prefix within CTA

    asm volatile("barrier.cluster.wait.aligned;" ::: "memory");

    // ---------------- cross-CTA base + n_observed ---------------------------
    float ctaExcl = 0.f, nObs = 0.f;
    #pragma unroll
    for (int j = 0; j < NC; j++) {
        if ((unsigned)j < rank) ctaExcl += s_tot[j].x;
        nObs += s_tot[j].y;
    }

    // ---------------- masked contributions (fast log) -----------------------
    const float base = ctaExcl + P;
    float c = 0.f;
    #pragma unroll
    for (int k = 0; k < VPT; k++) {
        if (ev[k] != 0.f) c += ev[k] * (p[k] - __logf(base + r[k]));
    }

    // ---------------- per-warp reduce + fire-and-forget REDG ----------------
    const float wc = warp_sum(c);
    if (lane == 0) {
        const float scale = (nObs == 0.f) ? 0.f : (-1.f / fmaxf(nObs, 1.f));
        red_add_f32(&out[0], wc * scale);      // 64 no-return atomics total
    }
    if (rank == 0 && t == 0 && out_size > 1) out[1] = nObs;
}

extern "C" void kernel_launch(void* const* d_in, const int* in_sizes, int n_in,
                              void* d_out, int out_size) {
    const float4* pred4  = (const float4*)d_in[0];
    const float4* label4 = (const float4*)d_in[1];
    float* out = (float*)d_out;

    nll_cluster<<<NC, T>>>(pred4, label4, out, out_size);
}